// round 14
// baseline (speedup 1.0000x reference)
#include <cuda_runtime.h>
#include <math.h>
#include <stdint.h>

#define BB 256
#define NN 2048
#define NSUM 22   // M(6 sym), C(9), mw(3), yw(3), wsum(1)

#define ROW_BYTES 8192                  // 2048 floats
#define TMA_BYTES (3 * ROW_BYTES)       // w, m0, m1 via TMA -> smem

// scratch (no allocations allowed)
__device__ float g_sq[BB];
__device__ unsigned int g_ctr;   // zero-init; monotonic across graph replays

// ---------------------------------------------------------------------------
// Closed-form eigenvector for symmetric A at eigenvalue lam (unnormalized).
// ---------------------------------------------------------------------------
__device__ __forceinline__ void eigvec_raw(const float A[3][3], float lam,
                                           float out[3])
{
    float b00 = A[0][0] - lam, b11 = A[1][1] - lam, b22 = A[2][2] - lam;
    float b01 = A[0][1], b02 = A[0][2], b12 = A[1][2];
    float c0[3] = { b01 * b12 - b02 * b11,
                    b02 * b01 - b00 * b12,
                    b00 * b11 - b01 * b01 };
    float c1[3] = { b01 * b22 - b02 * b12,
                    b02 * b02 - b00 * b22,
                    b00 * b12 - b02 * b01 };
    float c2[3] = { b11 * b22 - b12 * b12,
                    b12 * b02 - b01 * b22,
                    b01 * b12 - b11 * b02 };
    float n0 = c0[0]*c0[0] + c0[1]*c0[1] + c0[2]*c0[2];
    float n1 = c1[0]*c1[0] + c1[1]*c1[1] + c1[2]*c1[2];
    float n2 = c2[0]*c2[0] + c2[1]*c2[1] + c2[2]*c2[2];
    const float* best = c0;
    float nb = n0;
    if (n1 > nb) { best = c1; nb = n1; }
    if (n2 > nb) { best = c2; }
    out[0] = best[0]; out[1] = best[1]; out[2] = best[2];
}

// ---------------------------------------------------------------------------
// Pose solve: closed-form (Cardano) 3x3 symmetric eigensolve.
// ---------------------------------------------------------------------------
__device__ void solve_pose(const float* __restrict__ s,
                           const float* __restrict__ tsv_in,
                           float* __restrict__ ob)
{
    float inv_ws = __fdividef(1.f, s[21]);
    float mw[3] = {s[15], s[16], s[17]};
    float yw[3] = {s[18], s[19], s[20]};

    float H[3][3];
#pragma unroll
    for (int i = 0; i < 3; i++)
#pragma unroll
        for (int j = 0; j < 3; j++)
            H[i][j] = s[6 + 3 * j + i] - yw[i] * mw[j] * inv_ws;

    float mum[3], muy[3];
#pragma unroll
    for (int i = 0; i < 3; i++) { mum[i] = mw[i] * inv_ws; muy[i] = yw[i] * inv_ws; }

    float A[3][3];
#pragma unroll
    for (int i = 0; i < 3; i++)
#pragma unroll
        for (int j = 0; j < 3; j++) {
            float tv = 0.f;
#pragma unroll
            for (int k = 0; k < 3; k++) tv += H[k][i] * H[k][j];
            A[i][j] = tv;
        }

    // Cardano eigenvalues
    float m = (A[0][0] + A[1][1] + A[2][2]) * (1.f / 3.f);
    float K00 = A[0][0] - m, K11 = A[1][1] - m, K22 = A[2][2] - m;
    float a01 = A[0][1], a02 = A[0][2], a12 = A[1][2];
    float p2 = (K00*K00 + K11*K11 + K22*K22) * (1.f / 6.f)
             + (a01*a01 + a02*a02 + a12*a12) * (1.f / 3.f);
    float p = sqrtf(fmaxf(p2, 1e-30f));
    float detK = K00 * (K11 * K22 - a12 * a12)
               - a01 * (a01 * K22 - a12 * a02)
               + a02 * (a01 * a12 - K11 * a02);
    float r = __fdividef(detK, 2.f * p * fmaxf(p2, 1e-30f));
    r = fminf(fmaxf(r, -1.f), 1.f);
    float phi = acosf(r) * (1.f / 3.f);
    float lam0   = m + 2.f * p * __cosf(phi);
    float lammin = m + 2.f * p * __cosf(phi + 2.09439510239f);
    float lam1   = 3.f * m - lam0 - lammin;

    float v0[3], v1r[3];
    eigvec_raw(A, lam0, v0);
    eigvec_raw(A, lam1, v1r);
    {
        float nv0 = rsqrtf(fmaxf(v0[0]*v0[0] + v0[1]*v0[1] + v0[2]*v0[2], 1e-30f));
#pragma unroll
        for (int i = 0; i < 3; i++) v0[i] *= nv0;
        float dotv = v0[0]*v1r[0] + v0[1]*v1r[1] + v0[2]*v1r[2];
#pragma unroll
        for (int i = 0; i < 3; i++) v1r[i] -= dotv * v0[i];
        float nv1 = rsqrtf(fmaxf(v1r[0]*v1r[0] + v1r[1]*v1r[1] + v1r[2]*v1r[2], 1e-30f));
#pragma unroll
        for (int i = 0; i < 3; i++) v1r[i] *= nv1;
    }
    float v2[3] = { v0[1]*v1r[2] - v0[2]*v1r[1],
                    v0[2]*v1r[0] - v0[0]*v1r[2],
                    v0[0]*v1r[1] - v0[1]*v1r[0] };

    float u0[3], u1[3], u2[3];
    {
        float t0[3], t1[3];
#pragma unroll
        for (int i = 0; i < 3; i++) {
            t0[i] = H[i][0] * v0[0]  + H[i][1] * v0[1]  + H[i][2] * v0[2];
            t1[i] = H[i][0] * v1r[0] + H[i][1] * v1r[1] + H[i][2] * v1r[2];
        }
        float n0 = rsqrtf(fmaxf(t0[0]*t0[0] + t0[1]*t0[1] + t0[2]*t0[2], 1e-30f));
#pragma unroll
        for (int i = 0; i < 3; i++) u0[i] = t0[i] * n0;
        float dotu = u0[0]*t1[0] + u0[1]*t1[1] + u0[2]*t1[2];
#pragma unroll
        for (int i = 0; i < 3; i++) t1[i] -= dotu * u0[i];
        float n1 = rsqrtf(fmaxf(t1[0]*t1[0] + t1[1]*t1[1] + t1[2]*t1[2], 1e-30f));
#pragma unroll
        for (int i = 0; i < 3; i++) u1[i] = t1[i] * n1;
        u2[0] = u0[1]*u1[2] - u0[2]*u1[1];
        u2[1] = u0[2]*u1[0] - u0[0]*u1[2];
        u2[2] = u0[0]*u1[1] - u0[1]*u1[0];
    }

    float R[3][3];
#pragma unroll
    for (int i = 0; i < 3; i++) {
        float ui0 = u0[i], ui1 = u1[i], ui2 = u2[i];
#pragma unroll
        for (int j = 0; j < 3; j++)
            R[i][j] = ui0 * v0[j] + ui1 * v1r[j] + ui2 * v2[j];
    }

    float tt[3];
#pragma unroll
    for (int i = 0; i < 3; i++)
        tt[i] = R[i][0] * mum[0] + R[i][1] * mum[1] + R[i][2] * mum[2] - muy[i];

    float T[4][4];
#pragma unroll
    for (int i = 0; i < 3; i++) {
#pragma unroll
        for (int j = 0; j < 3; j++) T[i][j] = R[i][j];
        T[i][3] = -tt[i];
    }
    T[3][0] = 0.f; T[3][1] = 0.f; T[3][2] = 0.f; T[3][3] = 1.f;

    float Tsv[4][4];
#pragma unroll
    for (int i = 0; i < 4; i++)
#pragma unroll
        for (int j = 0; j < 4; j++) Tsv[i][j] = tsv_in[i * 4 + j];

    float Tinv[4][4];
#pragma unroll
    for (int i = 0; i < 3; i++) {
#pragma unroll
        for (int j = 0; j < 3; j++) Tinv[i][j] = Tsv[j][i];
        Tinv[i][3] = -(Tsv[0][i] * Tsv[0][3] + Tsv[1][i] * Tsv[1][3] + Tsv[2][i] * Tsv[2][3]);
    }
    Tinv[3][0] = 0.f; Tinv[3][1] = 0.f; Tinv[3][2] = 0.f; Tinv[3][3] = 1.f;

    float M1[4][4];
#pragma unroll
    for (int i = 0; i < 4; i++)
#pragma unroll
        for (int j = 0; j < 4; j++) {
            float tv = 0.f;
#pragma unroll
            for (int k = 0; k < 4; k++) tv += Tinv[i][k] * T[k][j];
            M1[i][j] = tv;
        }
#pragma unroll
    for (int i = 0; i < 4; i++)
#pragma unroll
        for (int j = 0; j < 4; j++) {
            float tv = 0.f;
#pragma unroll
            for (int k = 0; k < 4; k++) tv += M1[i][k] * Tsv[k][j];
            ob[i * 4 + j] = tv;
        }
}

// ---------------------------------------------------------------------------
__device__ __forceinline__ int sym6(int a, int c) {
    if (a > c) { int t = a; a = c; c = t; }
    return (a == 0) ? c : (a == 1) ? (2 + c) : 5;
}

__device__ __forceinline__ float q_entry(const float* __restrict__ ss, int e)
{
    int i = e / 13, j = e % 13;
    float val = 0.f;
    if (i == 0 && j == 0) {
        val = 0.f;
    } else if (i == 0 && j <= 9) {
        val = -ss[6 + (j - 1)];
    } else if (i == 0) {
        val = ss[18 + (j - 10)];
    } else if (j == 0 && i <= 9) {
        val = -ss[6 + (i - 1)];
    } else if (j == 0) {
        val = ss[18 + (i - 10)];
    } else if (i <= 9 && j <= 9) {
        int a = (i - 1) / 3, r = (i - 1) % 3;
        int bb2 = (j - 1) / 3, c = (j - 1) % 3;
        if (r == c) val = ss[sym6(a, bb2)];
    } else if (i <= 9) {
        int a = (i - 1) / 3, r = (i - 1) % 3, c = j - 10;
        if (r == c) val = -ss[15 + a];
    } else if (j <= 9) {
        int a = (j - 1) / 3, r = (j - 1) % 3, c = i - 10;
        if (r == c) val = -ss[15 + a];
    } else {
        if (i == j) val = ss[21];
    }
    return val;
}

// ---------------------------------------------------------------------------
// SINGLE fused kernel, HYBRID load path: w/m0/m1 via 3x cp.async.bulk (TMA
// engine) while m2/y0/y1/y2 stream via 8 front-batched LDG.128 (MSHR path).
// If the two paths have independent throughput caps, they overlap additively.
//
// 256 blocks x 256 threads, __launch_bounds__(256,2); smem/block ~25.6 KB ->
// 2 blocks/SM -> all 256 blocks co-resident -> ticket-spin deadlock-free.
// ---------------------------------------------------------------------------
extern __shared__ char dyn_smem[];

__global__ __launch_bounds__(256, 2) void fused_all(
    const float* __restrict__ src, const float* __restrict__ trg,
    const float* __restrict__ w, const float* __restrict__ tsv,
    float* __restrict__ tout, float* __restrict__ qout)
{
    int b = blockIdx.x;

    __shared__ uint64_t mbar;
    __shared__ float sm[8][NSUM];
    __shared__ float sfin[NSUM];
    __shared__ float s_inv;

    uint32_t mbar_addr;
    asm("{ .reg .u64 t; cvta.to.shared.u64 t, %1; cvt.u32.u64 %0, t; }"
        : "=r"(mbar_addr) : "l"(&mbar));
    uint32_t smem_base;
    asm("{ .reg .u64 t; cvta.to.shared.u64 t, %1; cvt.u32.u64 %0, t; }"
        : "=r"(smem_base) : "l"(dyn_smem));

    // ---- TMA: w, m0, m1 (8 KB each) ----
    if (threadIdx.x == 0) {
        asm volatile("mbarrier.init.shared.b64 [%0], %1;"
                     :: "r"(mbar_addr), "r"(1) : "memory");
    }
    __syncthreads();
    if (threadIdx.x == 0) {
        asm volatile("mbarrier.arrive.expect_tx.shared.b64 _, [%0], %1;"
                     :: "r"(mbar_addr), "r"((uint32_t)TMA_BYTES) : "memory");
        const char* g_w = (const char*)(w   + (size_t)b * NN);
        const char* g_m = (const char*)(src + (size_t)b * 4 * NN);
        const char* srcs[3] = { g_w, g_m, g_m + ROW_BYTES };
#pragma unroll
        for (int i = 0; i < 3; i++) {
            asm volatile(
                "cp.async.bulk.shared::cta.global.mbarrier::complete_tx::bytes "
                "[%0], [%1], %2, [%3];"
                :: "r"(smem_base + i * ROW_BYTES), "l"(srcs[i]),
                   "r"((uint32_t)ROW_BYTES), "r"(mbar_addr)
                : "memory");
        }
    }

    // ---- LDG: m2, y0, y1, y2 (front-batched, 8 LDG.128/thread) ----
    const int NV = NN / 4;  // 512 float4 per row
    const float4* m2 = (const float4*)(src + (size_t)b * 4 * NN + 2 * NN);
    const float4* y0 = (const float4*)(trg + (size_t)b * 4 * NN);
    const float4* y1 = y0 + NV;
    const float4* y2 = y0 + 2 * NV;
    int n0 = threadIdx.x;
    int n1 = threadIdx.x + 256;

    float4 a2A = __ldg(m2 + n0), c0A = __ldg(y0 + n0),
           c1A = __ldg(y1 + n0), c2A = __ldg(y2 + n0);
    float4 a2B = __ldg(m2 + n1), c0B = __ldg(y0 + n1),
           c1B = __ldg(y1 + n1), c2B = __ldg(y2 + n1);

    // ---- wait for TMA bytes ----
    {
        uint32_t done;
        asm volatile(
            "{\n\t"
            ".reg .pred p;\n\t"
            "mbarrier.try_wait.parity.acquire.cta.shared::cta.b64 p, [%1], 0;\n\t"
            "selp.b32 %0, 1, 0, p;\n\t"
            "}"
            : "=r"(done) : "r"(mbar_addr) : "memory");
        if (!done) {
            asm volatile(
                "{\n\t"
                ".reg .pred P1;\n\t"
                "WAIT_LOOP_%=:\n\t"
                "mbarrier.try_wait.parity.acquire.cta.shared::cta.b64 P1, [%0], 0, 0x989680;\n\t"
                "@P1 bra.uni WAIT_DONE_%=;\n\t"
                "bra.uni WAIT_LOOP_%=;\n\t"
                "WAIT_DONE_%=:\n\t"
                "}"
                :: "r"(mbar_addr) : "memory");
        }
    }

    const float4* Wv = (const float4*)(dyn_smem);
    const float4* M0 = (const float4*)(dyn_smem + 1 * ROW_BYTES);
    const float4* M1 = (const float4*)(dyn_smem + 2 * ROW_BYTES);

    float acc[NSUM];
#pragma unroll
    for (int k = 0; k < NSUM; k++) acc[k] = 0.f;

#pragma unroll
    for (int it = 0; it < 2; it++) {
        int n = (it == 0) ? n0 : n1;
        float4 wv4 = Wv[n];
        float4 a04 = M0[n], a14 = M1[n];
        float4 a24 = (it == 0) ? a2A : a2B;
        float4 c04 = (it == 0) ? c0A : c0B;
        float4 c14 = (it == 0) ? c1A : c1B;
        float4 c24 = (it == 0) ? c2A : c2B;
        const float* wvp = &wv4.x;
        const float* a0p = &a04.x; const float* a1p = &a14.x; const float* a2p = &a24.x;
        const float* c0p = &c04.x; const float* c1p = &c14.x; const float* c2p = &c24.x;
#pragma unroll
        for (int l = 0; l < 4; l++) {
            float wv = wvp[l];
            float a0 = a0p[l], a1 = a1p[l], a2 = a2p[l];
            float c0 = c0p[l], c1 = c1p[l], c2 = c2p[l];
            float w0 = wv * a0, w1 = wv * a1, w2 = wv * a2;
            acc[0]  += w0 * a0; acc[1]  += w0 * a1; acc[2]  += w0 * a2;
            acc[3]  += w1 * a1; acc[4]  += w1 * a2; acc[5]  += w2 * a2;
            acc[6]  += w0 * c0; acc[7]  += w0 * c1; acc[8]  += w0 * c2;
            acc[9]  += w1 * c0; acc[10] += w1 * c1; acc[11] += w1 * c2;
            acc[12] += w2 * c0; acc[13] += w2 * c1; acc[14] += w2 * c2;
            acc[15] += w0;      acc[16] += w1;      acc[17] += w2;
            acc[18] += wv * c0; acc[19] += wv * c1; acc[20] += wv * c2;
            acc[21] += wv;
        }
    }

    // warp reduce all 22
#pragma unroll
    for (int k = 0; k < NSUM; k++)
#pragma unroll
        for (int off = 16; off > 0; off >>= 1)
            acc[k] += __shfl_xor_sync(0xFFFFFFFFu, acc[k], off);

    int wid = threadIdx.x >> 5, lane = threadIdx.x & 31;
    if (lane == 0)
#pragma unroll
        for (int k = 0; k < NSUM; k++) sm[wid][k] = acc[k];
    __syncthreads();
    if (threadIdx.x < NSUM) {
        float s = 0.f;
#pragma unroll
        for (int ww = 0; ww < 8; ww++) s += sm[ww][threadIdx.x];
        sfin[threadIdx.x] = s;
    }
    __syncthreads();

    if (wid == 6) {
        // ---- pose (warp 6, lane 0): short Cardano chain, off the barrier ----
        if (lane == 0) solve_pose(sfin, tsv, tout + b * 16);
    } else if (wid == 7) {
        // ---- norm publish + grid-wide ticket sync + inv_scale broadcast ----
        unsigned int ticket = 0;
        if (lane == 0) {
            const float* s = sfin;
            float nq = 3.f * (s[0]*s[0] + s[3]*s[3] + s[5]*s[5])
                     + 6.f * (s[1]*s[1] + s[2]*s[2] + s[4]*s[4]);
#pragma unroll
            for (int k = 6; k < 15; k++) nq += 2.f * s[k] * s[k];
#pragma unroll
            for (int k = 15; k < 18; k++) nq += 6.f * s[k] * s[k];
#pragma unroll
            for (int k = 18; k < 21; k++) nq += 2.f * s[k] * s[k];
            nq += 3.f * s[21] * s[21];
            g_sq[b] = nq;
            __threadfence();
            ticket = atomicAdd(&g_ctr, 1u);
            unsigned int target = ((ticket >> 8) + 1u) << 8;  // next mult of 256
            while (*((volatile unsigned int*)&g_ctr) < target) { }
        }
        __syncwarp();
        __threadfence();
        float v = __ldcg(&g_sq[lane]) + __ldcg(&g_sq[lane + 32])
                + __ldcg(&g_sq[lane + 64]) + __ldcg(&g_sq[lane + 96])
                + __ldcg(&g_sq[lane + 128]) + __ldcg(&g_sq[lane + 160])
                + __ldcg(&g_sq[lane + 192]) + __ldcg(&g_sq[lane + 224]);
#pragma unroll
        for (int off = 16; off > 0; off >>= 1)
            v += __shfl_xor_sync(0xFFFFFFFFu, v, off);
        if (lane == 0) {
            float x = rsqrtf(v);
            x = x * (1.5f - 0.5f * v * x * x);  // Newton refine
            s_inv = x;
        }
        asm volatile("bar.sync 1, 224;" ::: "memory");
    } else {
        // ---- warps 0-5: precompute unscaled Q entry, then wait for scale ----
        float val = (threadIdx.x < 169) ? q_entry(sfin, threadIdx.x) : 0.f;
        asm volatile("bar.sync 1, 224;" ::: "memory");
        if (threadIdx.x < 169)
            qout[b * 169 + threadIdx.x] = val * s_inv;
    }
}

// ---------------------------------------------------------------------------
extern "C" void kernel_launch(void* const* d_in, const int* in_sizes, int n_in,
                              void* d_out, int out_size)
{
    const float* src = (const float*)d_in[0];
    const float* trg = (const float*)d_in[1];
    const float* w   = (const float*)d_in[2];
    const float* tsv = (const float*)d_in[3];
    float* out  = (float*)d_out;
    float* tout = out;                 // (B,4,4) = 4096 floats
    float* qout = out + BB * 16;       // (B,13,13) = 43264 floats

    cudaFuncSetAttribute(fused_all,
                         cudaFuncAttributeMaxDynamicSharedMemorySize,
                         TMA_BYTES);
    fused_all<<<BB, 256, TMA_BYTES>>>(src, trg, w, tsv, tout, qout);
}

// round 15
// speedup vs baseline: 1.0155x; 1.0155x over previous
#include <cuda_runtime.h>
#include <math.h>

#define BB 256
#define NN 2048
#define NSUM 22   // M(6 sym), C(9), mw(3), yw(3), wsum(1)

// scratch (no allocations allowed)
__device__ float g_sq[BB];
__device__ unsigned int g_ctr;   // zero-init; monotonic across graph replays

// Frobenius-norm multiplicity of each sum inside Q
__device__ __constant__ float NQ_COEF[NSUM] = {
    3.f, 6.f, 6.f, 3.f, 6.f, 3.f,             // M diag x3, off-diag x6
    2.f, 2.f, 2.f, 2.f, 2.f, 2.f, 2.f, 2.f, 2.f,  // C entries x2
    6.f, 6.f, 6.f,                            // mw x6
    2.f, 2.f, 2.f,                            // yw x2
    3.f                                       // wsum x3
};

// ---------------------------------------------------------------------------
// Closed-form eigenvector for symmetric A at eigenvalue lam (unnormalized).
// ---------------------------------------------------------------------------
__device__ __forceinline__ void eigvec_raw(const float A[3][3], float lam,
                                           float out[3])
{
    float b00 = A[0][0] - lam, b11 = A[1][1] - lam, b22 = A[2][2] - lam;
    float b01 = A[0][1], b02 = A[0][2], b12 = A[1][2];
    float c0[3] = { b01 * b12 - b02 * b11,
                    b02 * b01 - b00 * b12,
                    b00 * b11 - b01 * b01 };
    float c1[3] = { b01 * b22 - b02 * b12,
                    b02 * b02 - b00 * b22,
                    b00 * b12 - b02 * b01 };
    float c2[3] = { b11 * b22 - b12 * b12,
                    b12 * b02 - b01 * b22,
                    b01 * b12 - b11 * b02 };
    float n0 = c0[0]*c0[0] + c0[1]*c0[1] + c0[2]*c0[2];
    float n1 = c1[0]*c1[0] + c1[1]*c1[1] + c1[2]*c1[2];
    float n2 = c2[0]*c2[0] + c2[1]*c2[1] + c2[2]*c2[2];
    const float* best = c0;
    float nb = n0;
    if (n1 > nb) { best = c1; nb = n1; }
    if (n2 > nb) { best = c2; }
    out[0] = best[0]; out[1] = best[1]; out[2] = best[2];
}

// ---------------------------------------------------------------------------
// Pose solve: closed-form (Cardano) 3x3 symmetric eigensolve.
// ---------------------------------------------------------------------------
__device__ void solve_pose(const float* __restrict__ s,
                           const float* __restrict__ tsv_in,
                           float* __restrict__ ob)
{
    float inv_ws = __fdividef(1.f, s[21]);
    float mw[3] = {s[15], s[16], s[17]};
    float yw[3] = {s[18], s[19], s[20]};

    float H[3][3];
#pragma unroll
    for (int i = 0; i < 3; i++)
#pragma unroll
        for (int j = 0; j < 3; j++)
            H[i][j] = s[6 + 3 * j + i] - yw[i] * mw[j] * inv_ws;

    float mum[3], muy[3];
#pragma unroll
    for (int i = 0; i < 3; i++) { mum[i] = mw[i] * inv_ws; muy[i] = yw[i] * inv_ws; }

    float A[3][3];
#pragma unroll
    for (int i = 0; i < 3; i++)
#pragma unroll
        for (int j = 0; j < 3; j++) {
            float tv = 0.f;
#pragma unroll
            for (int k = 0; k < 3; k++) tv += H[k][i] * H[k][j];
            A[i][j] = tv;
        }

    // Cardano eigenvalues
    float m = (A[0][0] + A[1][1] + A[2][2]) * (1.f / 3.f);
    float K00 = A[0][0] - m, K11 = A[1][1] - m, K22 = A[2][2] - m;
    float a01 = A[0][1], a02 = A[0][2], a12 = A[1][2];
    float p2 = (K00*K00 + K11*K11 + K22*K22) * (1.f / 6.f)
             + (a01*a01 + a02*a02 + a12*a12) * (1.f / 3.f);
    float p = sqrtf(fmaxf(p2, 1e-30f));
    float detK = K00 * (K11 * K22 - a12 * a12)
               - a01 * (a01 * K22 - a12 * a02)
               + a02 * (a01 * a12 - K11 * a02);
    float r = __fdividef(detK, 2.f * p * fmaxf(p2, 1e-30f));
    r = fminf(fmaxf(r, -1.f), 1.f);
    float phi = acosf(r) * (1.f / 3.f);
    float lam0   = m + 2.f * p * __cosf(phi);
    float lammin = m + 2.f * p * __cosf(phi + 2.09439510239f);
    float lam1   = 3.f * m - lam0 - lammin;

    float v0[3], v1r[3];
    eigvec_raw(A, lam0, v0);
    eigvec_raw(A, lam1, v1r);
    {
        float nv0 = rsqrtf(fmaxf(v0[0]*v0[0] + v0[1]*v0[1] + v0[2]*v0[2], 1e-30f));
#pragma unroll
        for (int i = 0; i < 3; i++) v0[i] *= nv0;
        float dotv = v0[0]*v1r[0] + v0[1]*v1r[1] + v0[2]*v1r[2];
#pragma unroll
        for (int i = 0; i < 3; i++) v1r[i] -= dotv * v0[i];
        float nv1 = rsqrtf(fmaxf(v1r[0]*v1r[0] + v1r[1]*v1r[1] + v1r[2]*v1r[2], 1e-30f));
#pragma unroll
        for (int i = 0; i < 3; i++) v1r[i] *= nv1;
    }
    float v2[3] = { v0[1]*v1r[2] - v0[2]*v1r[1],
                    v0[2]*v1r[0] - v0[0]*v1r[2],
                    v0[0]*v1r[1] - v0[1]*v1r[0] };

    float u0[3], u1[3], u2[3];
    {
        float t0[3], t1[3];
#pragma unroll
        for (int i = 0; i < 3; i++) {
            t0[i] = H[i][0] * v0[0]  + H[i][1] * v0[1]  + H[i][2] * v0[2];
            t1[i] = H[i][0] * v1r[0] + H[i][1] * v1r[1] + H[i][2] * v1r[2];
        }
        float n0 = rsqrtf(fmaxf(t0[0]*t0[0] + t0[1]*t0[1] + t0[2]*t0[2], 1e-30f));
#pragma unroll
        for (int i = 0; i < 3; i++) u0[i] = t0[i] * n0;
        float dotu = u0[0]*t1[0] + u0[1]*t1[1] + u0[2]*t1[2];
#pragma unroll
        for (int i = 0; i < 3; i++) t1[i] -= dotu * u0[i];
        float n1 = rsqrtf(fmaxf(t1[0]*t1[0] + t1[1]*t1[1] + t1[2]*t1[2], 1e-30f));
#pragma unroll
        for (int i = 0; i < 3; i++) u1[i] = t1[i] * n1;
        u2[0] = u0[1]*u1[2] - u0[2]*u1[1];
        u2[1] = u0[2]*u1[0] - u0[0]*u1[2];
        u2[2] = u0[0]*u1[1] - u0[1]*u1[0];
    }

    float R[3][3];
#pragma unroll
    for (int i = 0; i < 3; i++) {
        float ui0 = u0[i], ui1 = u1[i], ui2 = u2[i];
#pragma unroll
        for (int j = 0; j < 3; j++)
            R[i][j] = ui0 * v0[j] + ui1 * v1r[j] + ui2 * v2[j];
    }

    float tt[3];
#pragma unroll
    for (int i = 0; i < 3; i++)
        tt[i] = R[i][0] * mum[0] + R[i][1] * mum[1] + R[i][2] * mum[2] - muy[i];

    float T[4][4];
#pragma unroll
    for (int i = 0; i < 3; i++) {
#pragma unroll
        for (int j = 0; j < 3; j++) T[i][j] = R[i][j];
        T[i][3] = -tt[i];
    }
    T[3][0] = 0.f; T[3][1] = 0.f; T[3][2] = 0.f; T[3][3] = 1.f;

    float Tsv[4][4];
#pragma unroll
    for (int i = 0; i < 4; i++)
#pragma unroll
        for (int j = 0; j < 4; j++) Tsv[i][j] = tsv_in[i * 4 + j];

    float Tinv[4][4];
#pragma unroll
    for (int i = 0; i < 3; i++) {
#pragma unroll
        for (int j = 0; j < 3; j++) Tinv[i][j] = Tsv[j][i];
        Tinv[i][3] = -(Tsv[0][i] * Tsv[0][3] + Tsv[1][i] * Tsv[1][3] + Tsv[2][i] * Tsv[2][3]);
    }
    Tinv[3][0] = 0.f; Tinv[3][1] = 0.f; Tinv[3][2] = 0.f; Tinv[3][3] = 1.f;

    float M1[4][4];
#pragma unroll
    for (int i = 0; i < 4; i++)
#pragma unroll
        for (int j = 0; j < 4; j++) {
            float tv = 0.f;
#pragma unroll
            for (int k = 0; k < 4; k++) tv += Tinv[i][k] * T[k][j];
            M1[i][j] = tv;
        }
#pragma unroll
    for (int i = 0; i < 4; i++)
#pragma unroll
        for (int j = 0; j < 4; j++) {
            float tv = 0.f;
#pragma unroll
            for (int k = 0; k < 4; k++) tv += M1[i][k] * Tsv[k][j];
            ob[i * 4 + j] = tv;
        }
}

// ---------------------------------------------------------------------------
__device__ __forceinline__ int sym6(int a, int c) {
    if (a > c) { int t = a; a = c; c = t; }
    return (a == 0) ? c : (a == 1) ? (2 + c) : 5;
}

__device__ __forceinline__ float q_entry(const float* __restrict__ ss, int e)
{
    int i = e / 13, j = e % 13;
    float val = 0.f;
    if (i == 0 && j == 0) {
        val = 0.f;
    } else if (i == 0 && j <= 9) {
        val = -ss[6 + (j - 1)];
    } else if (i == 0) {
        val = ss[18 + (j - 10)];
    } else if (j == 0 && i <= 9) {
        val = -ss[6 + (i - 1)];
    } else if (j == 0) {
        val = ss[18 + (i - 10)];
    } else if (i <= 9 && j <= 9) {
        int a = (i - 1) / 3, r = (i - 1) % 3;
        int bb2 = (j - 1) / 3, c = (j - 1) % 3;
        if (r == c) val = ss[sym6(a, bb2)];
    } else if (i <= 9) {
        int a = (i - 1) / 3, r = (i - 1) % 3, c = j - 10;
        if (r == c) val = -ss[15 + a];
    } else if (j <= 9) {
        int a = (j - 1) / 3, r = (j - 1) % 3, c = i - 10;
        if (r == c) val = -ss[15 + a];
    } else {
        if (i == j) val = ss[21];
    }
    return val;
}

// ---------------------------------------------------------------------------
// SINGLE fused kernel. 256 blocks x 256 threads, __launch_bounds__(256,2)
// -> 2 blocks/SM x 148 SMs = 296 slots >= 256 blocks co-resident -> the
// grid-wide ticket-spin cannot deadlock.
//
// Role split after block reduction:
//   warp 7 (224-255):  sfin combine + nq shuffle-reduce BEFORE sync2 (so the
//                      publish path has no serial recompute), then publish +
//                      ticket + spin + inv_scale -> smem, bar 1 (224)
//   warp 6 (192-223):  pose solve (Cardano; off the barrier)
//   warps 0-5 (0-191): precompute unscaled Q entry, bar 1 (224), scaled write
// ---------------------------------------------------------------------------
__global__ __launch_bounds__(256, 2) void fused_all(
    const float* __restrict__ src, const float* __restrict__ trg,
    const float* __restrict__ w, const float* __restrict__ tsv,
    float* __restrict__ tout, float* __restrict__ qout)
{
    int b = blockIdx.x;
    const int NV = NN / 4;  // 512 float4 per row; 256 threads -> 2 each
    const float4* m0 = (const float4*)(src + (size_t)b * 4 * NN);
    const float4* m1 = m0 + NV;
    const float4* m2 = m0 + 2 * NV;
    const float4* y0 = (const float4*)(trg + (size_t)b * 4 * NN);
    const float4* y1 = y0 + NV;
    const float4* y2 = y0 + 2 * NV;
    const float4* wp = (const float4*)(w + (size_t)b * NN);

    float acc[NSUM];
#pragma unroll
    for (int k = 0; k < NSUM; k++) acc[k] = 0.f;

#pragma unroll 2
    for (int n = threadIdx.x; n < NV; n += 256) {
        float4 wv4 = __ldcs(wp + n);
        float4 a04 = __ldcs(m0 + n), a14 = __ldcs(m1 + n), a24 = __ldcs(m2 + n);
        float4 c04 = __ldcs(y0 + n), c14 = __ldcs(y1 + n), c24 = __ldcs(y2 + n);
        const float* wvp = &wv4.x;
        const float* a0p = &a04.x; const float* a1p = &a14.x; const float* a2p = &a24.x;
        const float* c0p = &c04.x; const float* c1p = &c14.x; const float* c2p = &c24.x;
#pragma unroll
        for (int l = 0; l < 4; l++) {
            float wv = wvp[l];
            float a0 = a0p[l], a1 = a1p[l], a2 = a2p[l];
            float c0 = c0p[l], c1 = c1p[l], c2 = c2p[l];
            float w0 = wv * a0, w1 = wv * a1, w2 = wv * a2;
            acc[0]  += w0 * a0; acc[1]  += w0 * a1; acc[2]  += w0 * a2;
            acc[3]  += w1 * a1; acc[4]  += w1 * a2; acc[5]  += w2 * a2;
            acc[6]  += w0 * c0; acc[7]  += w0 * c1; acc[8]  += w0 * c2;
            acc[9]  += w1 * c0; acc[10] += w1 * c1; acc[11] += w1 * c2;
            acc[12] += w2 * c0; acc[13] += w2 * c1; acc[14] += w2 * c2;
            acc[15] += w0;      acc[16] += w1;      acc[17] += w2;
            acc[18] += wv * c0; acc[19] += wv * c1; acc[20] += wv * c2;
            acc[21] += wv;
        }
    }

    // warp reduce all 22
#pragma unroll
    for (int k = 0; k < NSUM; k++)
#pragma unroll
        for (int off = 16; off > 0; off >>= 1)
            acc[k] += __shfl_xor_sync(0xFFFFFFFFu, acc[k], off);

    __shared__ float sm[8][NSUM];
    __shared__ float sfin[NSUM];
    __shared__ float s_inv;
    int wid = threadIdx.x >> 5, lane = threadIdx.x & 31;
    if (lane == 0)
#pragma unroll
        for (int k = 0; k < NSUM; k++) sm[wid][k] = acc[k];
    __syncthreads();

    // warp 7: combine sums (lanes 0-21, parallel) + nq shuffle-reduce so the
    // publish after sync2 needs no serial recompute.
    float nq_part = 0.f;
    if (wid == 7) {
        if (lane < NSUM) {
            float s = 0.f;
#pragma unroll
            for (int ww = 0; ww < 8; ww++) s += sm[ww][lane];
            sfin[lane] = s;
            nq_part = NQ_COEF[lane] * s * s;
        }
#pragma unroll
        for (int off = 16; off > 0; off >>= 1)
            nq_part += __shfl_xor_sync(0xFFFFFFFFu, nq_part, off);
    }
    __syncthreads();

    if (wid == 6) {
        // ---- pose (warp 6, lane 0): short Cardano chain, off the barrier ----
        if (lane == 0) solve_pose(sfin, tsv, tout + b * 16);
    } else if (wid == 7) {
        // ---- publish (nq already in register) + ticket sync + scale ----
        if (lane == 0) {
            g_sq[b] = nq_part;
            __threadfence();
            unsigned int ticket = atomicAdd(&g_ctr, 1u);
            unsigned int target = ((ticket >> 8) + 1u) << 8;  // next mult of 256
            while (*((volatile unsigned int*)&g_ctr) < target) { }
        }
        __syncwarp();
        __threadfence();
        float v = __ldcg(&g_sq[lane]) + __ldcg(&g_sq[lane + 32])
                + __ldcg(&g_sq[lane + 64]) + __ldcg(&g_sq[lane + 96])
                + __ldcg(&g_sq[lane + 128]) + __ldcg(&g_sq[lane + 160])
                + __ldcg(&g_sq[lane + 192]) + __ldcg(&g_sq[lane + 224]);
#pragma unroll
        for (int off = 16; off > 0; off >>= 1)
            v += __shfl_xor_sync(0xFFFFFFFFu, v, off);
        if (lane == 0) {
            float x = rsqrtf(v);
            x = x * (1.5f - 0.5f * v * x * x);  // Newton refine
            s_inv = x;
        }
        asm volatile("bar.sync 1, 224;" ::: "memory");
    } else {
        // ---- warps 0-5: precompute unscaled Q entry, then wait for scale ----
        float val = (threadIdx.x < 169) ? q_entry(sfin, threadIdx.x) : 0.f;
        asm volatile("bar.sync 1, 224;" ::: "memory");
        if (threadIdx.x < 169)
            qout[b * 169 + threadIdx.x] = val * s_inv;
    }
}

// ---------------------------------------------------------------------------
extern "C" void kernel_launch(void* const* d_in, const int* in_sizes, int n_in,
                              void* d_out, int out_size)
{
    const float* src = (const float*)d_in[0];
    const float* trg = (const float*)d_in[1];
    const float* w   = (const float*)d_in[2];
    const float* tsv = (const float*)d_in[3];
    float* out  = (float*)d_out;
    float* tout = out;                 // (B,4,4) = 4096 floats
    float* qout = out + BB * 16;       // (B,13,13) = 43264 floats

    fused_all<<<BB, 256>>>(src, trg, w, tsv, tout, qout);
}

// round 16
// speedup vs baseline: 1.0864x; 1.0698x over previous
#include <cuda_runtime.h>
#include <math.h>

#define BB 256
#define NN 2048
#define NSUM 22   // M(6 sym), C(9), mw(3), yw(3), wsum(1)

// scratch (no allocations allowed)
__device__ float g_sq[BB];
__device__ unsigned int g_ctr;   // zero-init; monotonic across graph replays

// Frobenius-norm multiplicity of each sum inside Q
__device__ __constant__ float NQ_COEF[NSUM] = {
    3.f, 6.f, 6.f, 3.f, 6.f, 3.f,
    2.f, 2.f, 2.f, 2.f, 2.f, 2.f, 2.f, 2.f, 2.f,
    6.f, 6.f, 6.f,
    2.f, 2.f, 2.f,
    3.f
};

// ---------------------------------------------------------------------------
// Closed-form eigenvector for symmetric A at eigenvalue lam (unnormalized).
// ---------------------------------------------------------------------------
__device__ __forceinline__ void eigvec_raw(const float A[3][3], float lam,
                                           float out[3])
{
    float b00 = A[0][0] - lam, b11 = A[1][1] - lam, b22 = A[2][2] - lam;
    float b01 = A[0][1], b02 = A[0][2], b12 = A[1][2];
    float c0[3] = { b01 * b12 - b02 * b11,
                    b02 * b01 - b00 * b12,
                    b00 * b11 - b01 * b01 };
    float c1[3] = { b01 * b22 - b02 * b12,
                    b02 * b02 - b00 * b22,
                    b00 * b12 - b02 * b01 };
    float c2[3] = { b11 * b22 - b12 * b12,
                    b12 * b02 - b01 * b22,
                    b01 * b12 - b11 * b02 };
    float n0 = c0[0]*c0[0] + c0[1]*c0[1] + c0[2]*c0[2];
    float n1 = c1[0]*c1[0] + c1[1]*c1[1] + c1[2]*c1[2];
    float n2 = c2[0]*c2[0] + c2[1]*c2[1] + c2[2]*c2[2];
    const float* best = c0;
    float nb = n0;
    if (n1 > nb) { best = c1; nb = n1; }
    if (n2 > nb) { best = c2; }
    out[0] = best[0]; out[1] = best[1]; out[2] = best[2];
}

// ---------------------------------------------------------------------------
// Pose solve: closed-form (Cardano) 3x3 symmetric eigensolve.
// ---------------------------------------------------------------------------
__device__ void solve_pose(const float* __restrict__ s,
                           const float* __restrict__ tsv_in,
                           float* __restrict__ ob)
{
    float inv_ws = __fdividef(1.f, s[21]);
    float mw[3] = {s[15], s[16], s[17]};
    float yw[3] = {s[18], s[19], s[20]};

    float H[3][3];
#pragma unroll
    for (int i = 0; i < 3; i++)
#pragma unroll
        for (int j = 0; j < 3; j++)
            H[i][j] = s[6 + 3 * j + i] - yw[i] * mw[j] * inv_ws;

    float mum[3], muy[3];
#pragma unroll
    for (int i = 0; i < 3; i++) { mum[i] = mw[i] * inv_ws; muy[i] = yw[i] * inv_ws; }

    float A[3][3];
#pragma unroll
    for (int i = 0; i < 3; i++)
#pragma unroll
        for (int j = 0; j < 3; j++) {
            float tv = 0.f;
#pragma unroll
            for (int k = 0; k < 3; k++) tv += H[k][i] * H[k][j];
            A[i][j] = tv;
        }

    // Cardano eigenvalues
    float m = (A[0][0] + A[1][1] + A[2][2]) * (1.f / 3.f);
    float K00 = A[0][0] - m, K11 = A[1][1] - m, K22 = A[2][2] - m;
    float a01 = A[0][1], a02 = A[0][2], a12 = A[1][2];
    float p2 = (K00*K00 + K11*K11 + K22*K22) * (1.f / 6.f)
             + (a01*a01 + a02*a02 + a12*a12) * (1.f / 3.f);
    float p = sqrtf(fmaxf(p2, 1e-30f));
    float detK = K00 * (K11 * K22 - a12 * a12)
               - a01 * (a01 * K22 - a12 * a02)
               + a02 * (a01 * a12 - K11 * a02);
    float r = __fdividef(detK, 2.f * p * fmaxf(p2, 1e-30f));
    r = fminf(fmaxf(r, -1.f), 1.f);
    float phi = acosf(r) * (1.f / 3.f);
    float lam0   = m + 2.f * p * __cosf(phi);
    float lammin = m + 2.f * p * __cosf(phi + 2.09439510239f);
    float lam1   = 3.f * m - lam0 - lammin;

    float v0[3], v1r[3];
    eigvec_raw(A, lam0, v0);
    eigvec_raw(A, lam1, v1r);
    {
        float nv0 = rsqrtf(fmaxf(v0[0]*v0[0] + v0[1]*v0[1] + v0[2]*v0[2], 1e-30f));
#pragma unroll
        for (int i = 0; i < 3; i++) v0[i] *= nv0;
        float dotv = v0[0]*v1r[0] + v0[1]*v1r[1] + v0[2]*v1r[2];
#pragma unroll
        for (int i = 0; i < 3; i++) v1r[i] -= dotv * v0[i];
        float nv1 = rsqrtf(fmaxf(v1r[0]*v1r[0] + v1r[1]*v1r[1] + v1r[2]*v1r[2], 1e-30f));
#pragma unroll
        for (int i = 0; i < 3; i++) v1r[i] *= nv1;
    }
    float v2[3] = { v0[1]*v1r[2] - v0[2]*v1r[1],
                    v0[2]*v1r[0] - v0[0]*v1r[2],
                    v0[0]*v1r[1] - v0[1]*v1r[0] };

    float u0[3], u1[3], u2[3];
    {
        float t0[3], t1[3];
#pragma unroll
        for (int i = 0; i < 3; i++) {
            t0[i] = H[i][0] * v0[0]  + H[i][1] * v0[1]  + H[i][2] * v0[2];
            t1[i] = H[i][0] * v1r[0] + H[i][1] * v1r[1] + H[i][2] * v1r[2];
        }
        float n0 = rsqrtf(fmaxf(t0[0]*t0[0] + t0[1]*t0[1] + t0[2]*t0[2], 1e-30f));
#pragma unroll
        for (int i = 0; i < 3; i++) u0[i] = t0[i] * n0;
        float dotu = u0[0]*t1[0] + u0[1]*t1[1] + u0[2]*t1[2];
#pragma unroll
        for (int i = 0; i < 3; i++) t1[i] -= dotu * u0[i];
        float n1 = rsqrtf(fmaxf(t1[0]*t1[0] + t1[1]*t1[1] + t1[2]*t1[2], 1e-30f));
#pragma unroll
        for (int i = 0; i < 3; i++) u1[i] = t1[i] * n1;
        u2[0] = u0[1]*u1[2] - u0[2]*u1[1];
        u2[1] = u0[2]*u1[0] - u0[0]*u1[2];
        u2[2] = u0[0]*u1[1] - u0[1]*u1[0];
    }

    float R[3][3];
#pragma unroll
    for (int i = 0; i < 3; i++) {
        float ui0 = u0[i], ui1 = u1[i], ui2 = u2[i];
#pragma unroll
        for (int j = 0; j < 3; j++)
            R[i][j] = ui0 * v0[j] + ui1 * v1r[j] + ui2 * v2[j];
    }

    float tt[3];
#pragma unroll
    for (int i = 0; i < 3; i++)
        tt[i] = R[i][0] * mum[0] + R[i][1] * mum[1] + R[i][2] * mum[2] - muy[i];

    float T[4][4];
#pragma unroll
    for (int i = 0; i < 3; i++) {
#pragma unroll
        for (int j = 0; j < 3; j++) T[i][j] = R[i][j];
        T[i][3] = -tt[i];
    }
    T[3][0] = 0.f; T[3][1] = 0.f; T[3][2] = 0.f; T[3][3] = 1.f;

    float Tsv[4][4];
#pragma unroll
    for (int i = 0; i < 4; i++)
#pragma unroll
        for (int j = 0; j < 4; j++) Tsv[i][j] = tsv_in[i * 4 + j];

    float Tinv[4][4];
#pragma unroll
    for (int i = 0; i < 3; i++) {
#pragma unroll
        for (int j = 0; j < 3; j++) Tinv[i][j] = Tsv[j][i];
        Tinv[i][3] = -(Tsv[0][i] * Tsv[0][3] + Tsv[1][i] * Tsv[1][3] + Tsv[2][i] * Tsv[2][3]);
    }
    Tinv[3][0] = 0.f; Tinv[3][1] = 0.f; Tinv[3][2] = 0.f; Tinv[3][3] = 1.f;

    float M1[4][4];
#pragma unroll
    for (int i = 0; i < 4; i++)
#pragma unroll
        for (int j = 0; j < 4; j++) {
            float tv = 0.f;
#pragma unroll
            for (int k = 0; k < 4; k++) tv += Tinv[i][k] * T[k][j];
            M1[i][j] = tv;
        }
#pragma unroll
    for (int i = 0; i < 4; i++)
#pragma unroll
        for (int j = 0; j < 4; j++) {
            float tv = 0.f;
#pragma unroll
            for (int k = 0; k < 4; k++) tv += M1[i][k] * Tsv[k][j];
            ob[i * 4 + j] = tv;
        }
}

// ---------------------------------------------------------------------------
__device__ __forceinline__ int sym6(int a, int c) {
    if (a > c) { int t = a; a = c; c = t; }
    return (a == 0) ? c : (a == 1) ? (2 + c) : 5;
}

__device__ __forceinline__ float q_entry(const float* __restrict__ ss, int e)
{
    int i = e / 13, j = e % 13;
    float val = 0.f;
    if (i == 0 && j == 0) {
        val = 0.f;
    } else if (i == 0 && j <= 9) {
        val = -ss[6 + (j - 1)];
    } else if (i == 0) {
        val = ss[18 + (j - 10)];
    } else if (j == 0 && i <= 9) {
        val = -ss[6 + (i - 1)];
    } else if (j == 0) {
        val = ss[18 + (i - 10)];
    } else if (i <= 9 && j <= 9) {
        int a = (i - 1) / 3, r = (i - 1) % 3;
        int bb2 = (j - 1) / 3, c = (j - 1) % 3;
        if (r == c) val = ss[sym6(a, bb2)];
    } else if (i <= 9) {
        int a = (i - 1) / 3, r = (i - 1) % 3, c = j - 10;
        if (r == c) val = -ss[15 + a];
    } else if (j <= 9) {
        int a = (j - 1) / 3, r = (j - 1) % 3, c = i - 10;
        if (r == c) val = -ss[15 + a];
    } else {
        if (i == j) val = ss[21];
    }
    return val;
}

// ---------------------------------------------------------------------------
// SINGLE fused kernel. 256 blocks x 256 threads, __launch_bounds__(256,2)
// -> 2 blocks/SM x 148 SMs = 296 slots >= 256 blocks co-resident -> the
// grid-wide ticket-spin cannot deadlock.
//
// Sync primitives: release-scope RED for the ticket (no standalone membar on
// the serialized publish path), acquire loads + __nanosleep backoff on the
// spin (keeps the g_ctr L2 line free for the remaining publishers).
// ---------------------------------------------------------------------------
__global__ __launch_bounds__(256, 2) void fused_all(
    const float* __restrict__ src, const float* __restrict__ trg,
    const float* __restrict__ w, const float* __restrict__ tsv,
    float* __restrict__ tout, float* __restrict__ qout)
{
    int b = blockIdx.x;
    const int NV = NN / 4;  // 512 float4 per row; 256 threads -> 2 each
    const float4* m0 = (const float4*)(src + (size_t)b * 4 * NN);
    const float4* m1 = m0 + NV;
    const float4* m2 = m0 + 2 * NV;
    const float4* y0 = (const float4*)(trg + (size_t)b * 4 * NN);
    const float4* y1 = y0 + NV;
    const float4* y2 = y0 + 2 * NV;
    const float4* wp = (const float4*)(w + (size_t)b * NN);

    float acc[NSUM];
#pragma unroll
    for (int k = 0; k < NSUM; k++) acc[k] = 0.f;

#pragma unroll 2
    for (int n = threadIdx.x; n < NV; n += 256) {
        float4 wv4 = __ldcs(wp + n);
        float4 a04 = __ldcs(m0 + n), a14 = __ldcs(m1 + n), a24 = __ldcs(m2 + n);
        float4 c04 = __ldcs(y0 + n), c14 = __ldcs(y1 + n), c24 = __ldcs(y2 + n);
        const float* wvp = &wv4.x;
        const float* a0p = &a04.x; const float* a1p = &a14.x; const float* a2p = &a24.x;
        const float* c0p = &c04.x; const float* c1p = &c14.x; const float* c2p = &c24.x;
#pragma unroll
        for (int l = 0; l < 4; l++) {
            float wv = wvp[l];
            float a0 = a0p[l], a1 = a1p[l], a2 = a2p[l];
            float c0 = c0p[l], c1 = c1p[l], c2 = c2p[l];
            float w0 = wv * a0, w1 = wv * a1, w2 = wv * a2;
            acc[0]  += w0 * a0; acc[1]  += w0 * a1; acc[2]  += w0 * a2;
            acc[3]  += w1 * a1; acc[4]  += w1 * a2; acc[5]  += w2 * a2;
            acc[6]  += w0 * c0; acc[7]  += w0 * c1; acc[8]  += w0 * c2;
            acc[9]  += w1 * c0; acc[10] += w1 * c1; acc[11] += w1 * c2;
            acc[12] += w2 * c0; acc[13] += w2 * c1; acc[14] += w2 * c2;
            acc[15] += w0;      acc[16] += w1;      acc[17] += w2;
            acc[18] += wv * c0; acc[19] += wv * c1; acc[20] += wv * c2;
            acc[21] += wv;
        }
    }

    // warp reduce all 22
#pragma unroll
    for (int k = 0; k < NSUM; k++)
#pragma unroll
        for (int off = 16; off > 0; off >>= 1)
            acc[k] += __shfl_xor_sync(0xFFFFFFFFu, acc[k], off);

    __shared__ float sm[8][NSUM];
    __shared__ float sfin[NSUM];
    __shared__ float s_inv;
    int wid = threadIdx.x >> 5, lane = threadIdx.x & 31;
    if (lane == 0)
#pragma unroll
        for (int k = 0; k < NSUM; k++) sm[wid][k] = acc[k];
    __syncthreads();

    // warp 7: combine sums (lanes 0-21, parallel) + nq shuffle-reduce so the
    // publish after sync2 needs no serial recompute.
    float nq_part = 0.f;
    if (wid == 7) {
        if (lane < NSUM) {
            float s = 0.f;
#pragma unroll
            for (int ww = 0; ww < 8; ww++) s += sm[ww][lane];
            sfin[lane] = s;
            nq_part = NQ_COEF[lane] * s * s;
        }
#pragma unroll
        for (int off = 16; off > 0; off >>= 1)
            nq_part += __shfl_xor_sync(0xFFFFFFFFu, nq_part, off);
    }
    __syncthreads();

    if (wid == 6) {
        // ---- pose (warp 6, lane 0): short Cardano chain, off the barrier ----
        if (lane == 0) solve_pose(sfin, tsv, tout + b * 16);
    } else if (wid == 7) {
        // ---- publish with release semantics + backoff spin with acquire ----
        if (lane == 0) {
            g_sq[b] = nq_part;
            // release-RED: orders the g_sq store without a standalone membar
            asm volatile("red.release.gpu.global.add.u32 [%0], %1;"
                         :: "l"(&g_ctr), "r"(1u) : "memory");
            // acquire-poll with HW-sleep backoff (frees the line for publishers)
            unsigned int cur;
            asm volatile("ld.acquire.gpu.global.u32 %0, [%1];"
                         : "=r"(cur) : "l"(&g_ctr) : "memory");
            // target = next multiple of 256 at-or-above current epoch progress:
            // our own increment is included in cur (>= epoch*256+1)
            unsigned int target = ((cur - 1u) / 256u + 1u) * 256u;
            while (cur < target) {
                __nanosleep(64);
                asm volatile("ld.acquire.gpu.global.u32 %0, [%1];"
                             : "=r"(cur) : "l"(&g_ctr) : "memory");
            }
        }
        __syncwarp();
        float v = __ldcg(&g_sq[lane]) + __ldcg(&g_sq[lane + 32])
                + __ldcg(&g_sq[lane + 64]) + __ldcg(&g_sq[lane + 96])
                + __ldcg(&g_sq[lane + 128]) + __ldcg(&g_sq[lane + 160])
                + __ldcg(&g_sq[lane + 192]) + __ldcg(&g_sq[lane + 224]);
#pragma unroll
        for (int off = 16; off > 0; off >>= 1)
            v += __shfl_xor_sync(0xFFFFFFFFu, v, off);
        if (lane == 0) {
            float x = rsqrtf(v);
            x = x * (1.5f - 0.5f * v * x * x);  // Newton refine
            s_inv = x;
        }
        asm volatile("bar.sync 1, 224;" ::: "memory");
    } else {
        // ---- warps 0-5: precompute unscaled Q entry, then wait for scale ----
        float val = (threadIdx.x < 169) ? q_entry(sfin, threadIdx.x) : 0.f;
        asm volatile("bar.sync 1, 224;" ::: "memory");
        if (threadIdx.x < 169)
            qout[b * 169 + threadIdx.x] = val * s_inv;
    }
}

// ---------------------------------------------------------------------------
extern "C" void kernel_launch(void* const* d_in, const int* in_sizes, int n_in,
                              void* d_out, int out_size)
{
    const float* src = (const float*)d_in[0];
    const float* trg = (const float*)d_in[1];
    const float* w   = (const float*)d_in[2];
    const float* tsv = (const float*)d_in[3];
    float* out  = (float*)d_out;
    float* tout = out;                 // (B,4,4) = 4096 floats
    float* qout = out + BB * 16;       // (B,13,13) = 43264 floats

    fused_all<<<BB, 256>>>(src, trg, w, tsv, tout, qout);
}